// round 2
// baseline (speedup 1.0000x reference)
#include <cuda_runtime.h>

#define NT 256          // threads per CTA
#define TT 48           // encoder timesteps
#define FUT 48          // decoder steps
#define NNODE 32
#define INF 11
#define HH 64
#define LDA 68          // padded activation row stride (floats)

// ---------------------------------------------------------------------------
// packed fp32x2 FMA (Blackwell FFMA2) — ptxas only emits it from PTX f32x2
// ---------------------------------------------------------------------------
__device__ __forceinline__ float2 ffma2(float2 a, float2 b, float2 c) {
  float2 d;
  asm("{\n\t"
      ".reg .b64 ra, rb, rc, rd;\n\t"
      "mov.b64 ra, {%2, %3};\n\t"
      "mov.b64 rb, {%4, %5};\n\t"
      "mov.b64 rc, {%6, %7};\n\t"
      "fma.rn.f32x2 rd, ra, rb, rc;\n\t"
      "mov.b64 {%0, %1}, rd;\n\t"
      "}"
      : "=f"(d.x), "=f"(d.y)
      : "f"(a.x), "f"(a.y), "f"(b.x), "f"(b.y), "f"(c.x), "f"(c.y));
  return d;
}

__device__ __forceinline__ float sigf(float x) {
  return __fdividef(1.0f, 1.0f + __expf(-x));
}
__device__ __forceinline__ float tanh_f(float x) {
  return __fdividef(2.0f, 1.0f + __expf(-2.0f * x)) - 1.0f;
}

struct __align__(16) Smem {
  float Ahat[32][36];     // padded rows (bank-conflict avoidance)
  float Wenc[11][64];
  float Wg1[64][64];
  float Wg2[64][64];
  float Wd1[64][32];
  float Wd2[32][8];       // padded
  float benc[64];
  float bg1[64];
  float bg2[64];
  float bd1[32];
  float bd2[8];
  float dvec[32];
  float xbuf[32][12];     // current input frame (pred|stat in decode)
  float act0[32][LDA];    // enc / tmp2
  float act1[32][LDA];    // tmp
  float act2[32][LDA];    // s / xf
  float hx[32][LDA];
  float cx[32][LDA];
  float g[32][256];       // LSTM pre-activations
  float h1[32][36];       // decoder hidden
};

// out[r][c0 .. c0+NO) = act( bias + sum_k A[k] * W[k*LDW + c] )
// A is a contiguous per-row vector; W rows are LDW-strided.
template<int K, int LDW, int NO, bool BIAS, bool RELU>
__device__ __forceinline__ void rowmm(const float* __restrict__ A,
                                      const float* __restrict__ W,
                                      const float* __restrict__ bias,
                                      float* __restrict__ outp, int c0) {
  float2 acc0, acc1, acc2, acc3;
  if (BIAS) {
    const float4* bp = reinterpret_cast<const float4*>(bias + c0);
    float4 b0 = bp[0];
    acc0 = make_float2(b0.x, b0.y); acc1 = make_float2(b0.z, b0.w);
    if (NO == 8) {
      float4 b1 = bp[1];
      acc2 = make_float2(b1.x, b1.y); acc3 = make_float2(b1.z, b1.w);
    } else { acc2 = acc3 = make_float2(0.f, 0.f); }
  } else {
    acc0 = acc1 = acc2 = acc3 = make_float2(0.f, 0.f);
  }
#pragma unroll 16
  for (int k = 0; k < K; k++) {
    float av = A[k];
    float2 aa = make_float2(av, av);
    const float4* wp = reinterpret_cast<const float4*>(W + k * LDW + c0);
    float4 w0 = wp[0];
    acc0 = ffma2(aa, make_float2(w0.x, w0.y), acc0);
    acc1 = ffma2(aa, make_float2(w0.z, w0.w), acc1);
    if (NO == 8) {
      float4 w1 = wp[1];
      acc2 = ffma2(aa, make_float2(w1.x, w1.y), acc2);
      acc3 = ffma2(aa, make_float2(w1.z, w1.w), acc3);
    }
  }
  float4 o0;
  o0.x = RELU ? fmaxf(acc0.x, 0.f) : acc0.x;
  o0.y = RELU ? fmaxf(acc0.y, 0.f) : acc0.y;
  o0.z = RELU ? fmaxf(acc1.x, 0.f) : acc1.x;
  o0.w = RELU ? fmaxf(acc1.y, 0.f) : acc1.y;
  *reinterpret_cast<float4*>(outp + c0) = o0;
  if (NO == 8) {
    float4 o1;
    o1.x = RELU ? fmaxf(acc2.x, 0.f) : acc2.x;
    o1.y = RELU ? fmaxf(acc2.y, 0.f) : acc2.y;
    o1.z = RELU ? fmaxf(acc3.x, 0.f) : acc3.x;
    o1.w = RELU ? fmaxf(acc3.y, 0.f) : acc3.y;
    *reinterpret_cast<float4*>(outp + c0 + 4) = o1;
  }
}

// spatial GCN (2 layers) + LSTM step. wih/whh: per-thread register-resident
// rows of W_ih / W_hh (thread tid owns gate column tid).
__device__ __forceinline__ void step_common(Smem& s, const float2* wih,
                                            const float2* whh, float bb,
                                            int tid) {
  const int r = tid >> 3;
  const int c0 = (tid & 7) * 8;

  // enc = relu(x @ W_enc + b_enc)
  rowmm<INF, 64, 8, true, true>(&s.xbuf[r][0], &s.Wenc[0][0], s.benc,
                                &s.act0[r][0], c0);
  __syncthreads();
  // tmp = enc @ W_g1
  rowmm<64, 64, 8, false, false>(&s.act0[r][0], &s.Wg1[0][0], nullptr,
                                 &s.act1[r][0], c0);
  __syncthreads();
  // s1 = relu(Ahat @ tmp + b_g1)
  rowmm<32, LDA, 8, true, true>(&s.Ahat[r][0], &s.act1[0][0], s.bg1,
                                &s.act2[r][0], c0);
  __syncthreads();
  // tmp2 = s1 @ W_g2
  rowmm<64, 64, 8, false, false>(&s.act2[r][0], &s.Wg2[0][0], nullptr,
                                 &s.act0[r][0], c0);
  __syncthreads();
  // xf = relu(Ahat @ tmp2 + b_g2)
  rowmm<32, LDA, 8, true, true>(&s.Ahat[r][0], &s.act0[0][0], s.bg2,
                                &s.act2[r][0], c0);
  __syncthreads();

  // LSTM: g[row][tid] = b + xf[row] . W_ih[tid] + hx[row] . W_hh[tid]
  for (int rr = 0; rr < 32; rr += 2) {
    const float4* x0 = reinterpret_cast<const float4*>(&s.act2[rr][0]);
    const float4* x1 = reinterpret_cast<const float4*>(&s.act2[rr + 1][0]);
    const float4* h0 = reinterpret_cast<const float4*>(&s.hx[rr][0]);
    const float4* h1p = reinterpret_cast<const float4*>(&s.hx[rr + 1][0]);
    float2 a0 = make_float2(0.f, 0.f), a1 = make_float2(0.f, 0.f);
    float2 b0 = make_float2(0.f, 0.f), b1 = make_float2(0.f, 0.f);
#pragma unroll
    for (int q = 0; q < 16; q++) {
      float4 xv0 = x0[q], hv0 = h0[q];
      a0 = ffma2(make_float2(xv0.x, xv0.y), wih[2 * q], a0);
      a1 = ffma2(make_float2(xv0.z, xv0.w), wih[2 * q + 1], a1);
      a0 = ffma2(make_float2(hv0.x, hv0.y), whh[2 * q], a0);
      a1 = ffma2(make_float2(hv0.z, hv0.w), whh[2 * q + 1], a1);
      float4 xv1 = x1[q], hv1 = h1p[q];
      b0 = ffma2(make_float2(xv1.x, xv1.y), wih[2 * q], b0);
      b1 = ffma2(make_float2(xv1.z, xv1.w), wih[2 * q + 1], b1);
      b0 = ffma2(make_float2(hv1.x, hv1.y), whh[2 * q], b0);
      b1 = ffma2(make_float2(hv1.z, hv1.w), whh[2 * q + 1], b1);
    }
    s.g[rr][tid]     = bb + a0.x + a0.y + a1.x + a1.y;
    s.g[rr + 1][tid] = bb + b0.x + b0.y + b1.x + b1.y;
  }
  __syncthreads();

  // gate nonlinearity + state update
  {
#pragma unroll
    for (int h4 = 0; h4 < 2; h4++) {
      int c = c0 + h4 * 4;
      float4 gi = *reinterpret_cast<const float4*>(&s.g[r][c]);
      float4 gf = *reinterpret_cast<const float4*>(&s.g[r][64 + c]);
      float4 gg = *reinterpret_cast<const float4*>(&s.g[r][128 + c]);
      float4 go = *reinterpret_cast<const float4*>(&s.g[r][192 + c]);
      float4 cc = *reinterpret_cast<const float4*>(&s.cx[r][c]);
      float4 cn, hn;
      cn.x = sigf(gf.x) * cc.x + sigf(gi.x) * tanh_f(gg.x);
      cn.y = sigf(gf.y) * cc.y + sigf(gi.y) * tanh_f(gg.y);
      cn.z = sigf(gf.z) * cc.z + sigf(gi.z) * tanh_f(gg.z);
      cn.w = sigf(gf.w) * cc.w + sigf(gi.w) * tanh_f(gg.w);
      hn.x = sigf(go.x) * tanh_f(cn.x);
      hn.y = sigf(go.y) * tanh_f(cn.y);
      hn.z = sigf(go.z) * tanh_f(cn.z);
      hn.w = sigf(go.w) * tanh_f(cn.w);
      *reinterpret_cast<float4*>(&s.cx[r][c]) = cn;
      *reinterpret_cast<float4*>(&s.hx[r][c]) = hn;
    }
  }
  __syncthreads();
}

__global__ void __launch_bounds__(NT, 1)
stgnn_kernel(const float* __restrict__ x, const float* __restrict__ adj,
             const float* __restrict__ Wenc_g, const float* __restrict__ benc_g,
             const float* __restrict__ Wg1_g, const float* __restrict__ bg1_g,
             const float* __restrict__ Wg2_g, const float* __restrict__ bg2_g,
             const float* __restrict__ Wih_g, const float* __restrict__ Whh_g,
             const float* __restrict__ bih_g, const float* __restrict__ bhh_g,
             const float* __restrict__ Wd1_g, const float* __restrict__ bd1_g,
             const float* __restrict__ Wd2_g, const float* __restrict__ bd2_g,
             float* __restrict__ out) {
  extern __shared__ __align__(16) unsigned char smem_raw[];
  Smem& s = *reinterpret_cast<Smem*>(smem_raw);
  const int tid = threadIdx.x;
  const int b = blockIdx.x;

  // ---- one-time per-CTA setup ----
  for (int i = tid; i < INF * 64; i += NT) (&s.Wenc[0][0])[i] = Wenc_g[i];
  for (int i = tid; i < 64 * 64; i += NT) (&s.Wg1[0][0])[i] = Wg1_g[i];
  for (int i = tid; i < 64 * 64; i += NT) (&s.Wg2[0][0])[i] = Wg2_g[i];
  for (int i = tid; i < 64 * 32; i += NT) (&s.Wd1[0][0])[i] = Wd1_g[i];
  if (tid < 192) s.Wd2[tid / 6][tid % 6] = Wd2_g[tid];
  if (tid < 64) {
    s.benc[tid] = benc_g[tid];
    s.bg1[tid] = bg1_g[tid];
    s.bg2[tid] = bg2_g[tid];
  }
  if (tid < 32) s.bd1[tid] = bd1_g[tid];
  if (tid < 6) s.bd2[tid] = bd2_g[tid];
  if (tid < 32) {
    float sum = 0.f;
    for (int j = 0; j < 32; j++) sum += (j == tid) ? 1.f : adj[tid * 32 + j];
    s.dvec[tid] = rsqrtf(fmaxf(sum, 1.f));
  }
  for (int i = tid; i < 32 * LDA; i += NT) {
    (&s.hx[0][0])[i] = 0.f;
    (&s.cx[0][0])[i] = 0.f;
  }
  __syncthreads();
  for (int i = tid; i < 32 * 32; i += NT) {
    int ii = i >> 5, jj = i & 31;
    float a = (ii == jj) ? 1.f : adj[i];
    s.Ahat[ii][jj] = s.dvec[ii] * a * s.dvec[jj];
  }

  // LSTM weights: thread tid owns gate column tid -> 128 registers
  float2 wih[32], whh[32];
  {
    const float4* p = reinterpret_cast<const float4*>(Wih_g + tid * 64);
    const float4* q = reinterpret_cast<const float4*>(Whh_g + tid * 64);
#pragma unroll
    for (int i = 0; i < 16; i++) {
      float4 v = p[i];
      wih[2 * i] = make_float2(v.x, v.y);
      wih[2 * i + 1] = make_float2(v.z, v.w);
      float4 u = q[i];
      whh[2 * i] = make_float2(u.x, u.y);
      whh[2 * i + 1] = make_float2(u.z, u.w);
    }
  }
  const float bb = bih_g[tid] + bhh_g[tid];
  __syncthreads();

  // ---- encoder: 48 steps ----
  for (int t = 0; t < TT; t++) {
    const float* xt = x + ((size_t)b * TT + t) * (NNODE * INF);
    for (int i = tid; i < NNODE * INF; i += NT)
      s.xbuf[i / INF][i % INF] = xt[i];
    __syncthreads();
    step_common(s, wih, whh, bb, tid);
  }

  // ---- decoder: 48 steps (xbuf currently holds last frame = pred|stat) ----
  const int r = tid >> 3;
  for (int f = 0; f < FUT; f++) {
    step_common(s, wih, whh, bb, tid);
    // h1 = relu(hx @ W_d1 + b_d1)   (32x32)
    {
      int c0 = (tid & 7) * 4;
      rowmm<64, 32, 4, true, true>(&s.hx[r][0], &s.Wd1[0][0], s.bd1,
                                   &s.h1[r][0], c0);
    }
    __syncthreads();
    // res = h1 @ W_d2 + b_d2 ; pred += res ; emit
    if (tid < 192) {
      int rr = tid / 6, d = tid - rr * 6;
      float acc = s.bd2[d];
#pragma unroll
      for (int k = 0; k < 32; k++) acc += s.h1[rr][k] * s.Wd2[k][d];
      float p = s.xbuf[rr][d] + acc;
      s.xbuf[rr][d] = p;
      out[(((size_t)b * FUT + f) * NNODE + rr) * 6 + d] = p;
    }
    __syncthreads();
  }
}

extern "C" void kernel_launch(void* const* d_in, const int* in_sizes, int n_in,
                              void* d_out, int out_size) {
  const float* x     = (const float*)d_in[0];
  const float* adj   = (const float*)d_in[1];
  const float* Wenc  = (const float*)d_in[2];
  const float* benc  = (const float*)d_in[3];
  const float* Wg1   = (const float*)d_in[4];
  const float* bg1   = (const float*)d_in[5];
  const float* Wg2   = (const float*)d_in[6];
  const float* bg2   = (const float*)d_in[7];
  const float* Wih   = (const float*)d_in[8];
  const float* Whh   = (const float*)d_in[9];
  const float* bih   = (const float*)d_in[10];
  const float* bhh   = (const float*)d_in[11];
  const float* Wd1   = (const float*)d_in[12];
  const float* bd1   = (const float*)d_in[13];
  const float* Wd2   = (const float*)d_in[14];
  const float* bd2   = (const float*)d_in[15];
  float* out = (float*)d_out;

  int B = in_sizes[0] / (TT * NNODE * INF);

  cudaFuncSetAttribute(stgnn_kernel,
                       cudaFuncAttributeMaxDynamicSharedMemorySize,
                       (int)sizeof(Smem));
  stgnn_kernel<<<B, NT, sizeof(Smem)>>>(x, adj, Wenc, benc, Wg1, bg1, Wg2, bg2,
                                        Wih, Whh, bih, bhh, Wd1, bd1, Wd2, bd2,
                                        out);
}

// round 4
// speedup vs baseline: 1.0068x; 1.0068x over previous
#include <cuda_runtime.h>

#define NT 256          // threads per CTA
#define TT 48           // encoder timesteps
#define FUT 48          // decoder steps
#define NNODE 32
#define INF 11
#define LDA 68          // padded activation row stride (floats)
#define LDGR 260        // padded g row stride (floats), 260 % 32 == 4

// ---------------------------------------------------------------------------
// packed fp32x2 carried as b64 (no per-op mov.b64 pack/unpack)
// ---------------------------------------------------------------------------
typedef unsigned long long p2;

__device__ __forceinline__ p2 ffma2p(p2 a, p2 b, p2 c) {
  p2 d;
  asm("fma.rn.f32x2 %0, %1, %2, %3;" : "=l"(d) : "l"(a), "l"(b), "l"(c));
  return d;
}
__device__ __forceinline__ p2 add2p(p2 a, p2 b) {
  p2 d;
  asm("add.rn.f32x2 %0, %1, %2;" : "=l"(d) : "l"(a), "l"(b));
  return d;
}
__device__ __forceinline__ p2 pack2(float lo, float hi) {
  p2 d;
  asm("mov.b64 %0, {%1, %2};" : "=l"(d) : "f"(lo), "f"(hi));
  return d;
}
__device__ __forceinline__ float2 up2(p2 a) {
  float2 f;
  asm("mov.b64 {%0, %1}, %2;" : "=f"(f.x), "=f"(f.y) : "l"(a));
  return f;
}

__device__ __forceinline__ float sigf(float x) {
  return __fdividef(1.0f, 1.0f + __expf(-x));
}
__device__ __forceinline__ float tanh_f(float x) {
  return __fdividef(2.0f, 1.0f + __expf(-2.0f * x)) - 1.0f;
}

struct __align__(16) Smem {
  float Ahat[32][36];     // padded rows (36 % 32 == 4)
  float Wenc[11][64];
  float Wg1[64][64];
  float Wg2[64][64];
  float Wd1[64][32];
  float Wd2[32][8];       // padded
  float benc[64];
  float bg1[64];
  float bg2[64];
  float bd1[32];
  float bd2[8];
  float dvec[32];
  float xbuf[32][12];     // current input frame (pred|stat in decode)
  float act0[32][LDA];    // enc / tmp2
  float act1[32][LDA];    // tmp
  float act2[32][LDA];    // s / xf
  float hx[32][LDA];
  float cx[32][LDA];
  float g[32][LDGR];      // LSTM pre-activations (padded stride)
  float h1[32][36];       // decoder hidden
};

// out[r][c0 .. c0+NO) = act( bias + sum_k A[k] * W[k*LDW + c] )
// A is a contiguous per-row vector; W rows are LDW-strided. All FMA packed.
template<int K, int LDW, int NO, bool BIAS, bool RELU>
__device__ __forceinline__ void rowmm(const float* __restrict__ A,
                                      const float* __restrict__ W,
                                      const float* __restrict__ bias,
                                      float* __restrict__ outp, int c0) {
  p2 acc0, acc1, acc2, acc3;
  if (BIAS) {
    ulonglong2 b0 = *reinterpret_cast<const ulonglong2*>(bias + c0);
    acc0 = b0.x; acc1 = b0.y;
    if (NO == 8) {
      ulonglong2 b1 = *reinterpret_cast<const ulonglong2*>(bias + c0 + 4);
      acc2 = b1.x; acc3 = b1.y;
    } else { acc2 = 0ull; acc3 = 0ull; }
  } else {
    acc0 = acc1 = acc2 = acc3 = 0ull;
  }
#pragma unroll
  for (int k = 0; k < K; k++) {
    float av = A[k];
    p2 aa = pack2(av, av);                 // one MOV per k, feeds 2-4 FFMA2
    ulonglong2 w0 = *reinterpret_cast<const ulonglong2*>(W + k * LDW + c0);
    acc0 = ffma2p(aa, w0.x, acc0);
    acc1 = ffma2p(aa, w0.y, acc1);
    if (NO == 8) {
      ulonglong2 w1 = *reinterpret_cast<const ulonglong2*>(W + k * LDW + c0 + 4);
      acc2 = ffma2p(aa, w1.x, acc2);
      acc3 = ffma2p(aa, w1.y, acc3);
    }
  }
  float2 f0 = up2(acc0), f1 = up2(acc1);
  float4 o0;
  o0.x = RELU ? fmaxf(f0.x, 0.f) : f0.x;
  o0.y = RELU ? fmaxf(f0.y, 0.f) : f0.y;
  o0.z = RELU ? fmaxf(f1.x, 0.f) : f1.x;
  o0.w = RELU ? fmaxf(f1.y, 0.f) : f1.y;
  *reinterpret_cast<float4*>(outp + c0) = o0;
  if (NO == 8) {
    float2 f2 = up2(acc2), f3 = up2(acc3);
    float4 o1;
    o1.x = RELU ? fmaxf(f2.x, 0.f) : f2.x;
    o1.y = RELU ? fmaxf(f2.y, 0.f) : f2.y;
    o1.z = RELU ? fmaxf(f3.x, 0.f) : f3.x;
    o1.w = RELU ? fmaxf(f3.y, 0.f) : f3.y;
    *reinterpret_cast<float4*>(outp + c0 + 4) = o1;
  }
}

// spatial GCN (2 layers) + LSTM step. wih/whh: per-thread register-resident
// packed rows of W_ih / W_hh (thread tid owns gate column tid).
// Barrier policy: row r's 8 threads (tid = 8r..8r+7) are consecutive lanes of
// one warp, so row-local producer->consumer edges need only __syncwarp().
__device__ __forceinline__ void step_common(Smem& s, const p2* wih,
                                            const p2* whh, float bb, int tid) {
  const int r = tid >> 3;
  const int c0 = (tid & 7) * 8;

  // enc = relu(x @ W_enc + b_enc)          (consumers row-local)
  rowmm<INF, 64, 8, true, true>(&s.xbuf[r][0], &s.Wenc[0][0], s.benc,
                                &s.act0[r][0], c0);
  __syncwarp();
  // tmp = enc @ W_g1                        (consumers: all -> full barrier)
  rowmm<64, 64, 8, false, false>(&s.act0[r][0], &s.Wg1[0][0], nullptr,
                                 &s.act1[r][0], c0);
  __syncthreads();
  // s1 = relu(Ahat @ tmp + b_g1)            (consumers row-local)
  rowmm<32, LDA, 8, true, true>(&s.Ahat[r][0], &s.act1[0][0], s.bg1,
                                &s.act2[r][0], c0);
  __syncwarp();
  // tmp2 = s1 @ W_g2                        (consumers: all)
  rowmm<64, 64, 8, false, false>(&s.act2[r][0], &s.Wg2[0][0], nullptr,
                                 &s.act0[r][0], c0);
  __syncthreads();
  // xf = relu(Ahat @ tmp2 + b_g2)           (consumers: all, LSTM)
  rowmm<32, LDA, 8, true, true>(&s.Ahat[r][0], &s.act0[0][0], s.bg2,
                                &s.act2[r][0], c0);
  __syncthreads();

  // LSTM: g[row][tid] = b + xf[row].W_ih[tid] + hx[row].W_hh[tid]
  for (int rr = 0; rr < 32; rr += 2) {
    const ulonglong2* x0 = reinterpret_cast<const ulonglong2*>(&s.act2[rr][0]);
    const ulonglong2* x1 = reinterpret_cast<const ulonglong2*>(&s.act2[rr + 1][0]);
    const ulonglong2* h0 = reinterpret_cast<const ulonglong2*>(&s.hx[rr][0]);
    const ulonglong2* h1p = reinterpret_cast<const ulonglong2*>(&s.hx[rr + 1][0]);
    p2 a0 = 0ull, a1 = 0ull, b0 = 0ull, b1 = 0ull;
#pragma unroll
    for (int q = 0; q < 16; q++) {
      ulonglong2 xv0 = x0[q];
      a0 = ffma2p(xv0.x, wih[2 * q], a0);
      a1 = ffma2p(xv0.y, wih[2 * q + 1], a1);
      ulonglong2 hv0 = h0[q];
      a0 = ffma2p(hv0.x, whh[2 * q], a0);
      a1 = ffma2p(hv0.y, whh[2 * q + 1], a1);
      ulonglong2 xv1 = x1[q];
      b0 = ffma2p(xv1.x, wih[2 * q], b0);
      b1 = ffma2p(xv1.y, wih[2 * q + 1], b1);
      ulonglong2 hv1 = h1p[q];
      b0 = ffma2p(hv1.x, whh[2 * q], b0);
      b1 = ffma2p(hv1.y, whh[2 * q + 1], b1);
    }
    float2 fa = up2(add2p(a0, a1));
    s.g[rr][tid] = bb + fa.x + fa.y;
    float2 fb = up2(add2p(b0, b1));
    s.g[rr + 1][tid] = bb + fb.x + fb.y;
  }
  __syncthreads();

  // gate nonlinearity + state update (hx consumers this step are row-local;
  // cross-warp consumers (next LSTM) are covered by next step's barriers)
#pragma unroll
  for (int h4 = 0; h4 < 2; h4++) {
    int c = c0 + h4 * 4;
    float4 gi = *reinterpret_cast<const float4*>(&s.g[r][c]);
    float4 gf = *reinterpret_cast<const float4*>(&s.g[r][64 + c]);
    float4 gg = *reinterpret_cast<const float4*>(&s.g[r][128 + c]);
    float4 go = *reinterpret_cast<const float4*>(&s.g[r][192 + c]);
    float4 cc = *reinterpret_cast<const float4*>(&s.cx[r][c]);
    float4 cn, hn;
    cn.x = sigf(gf.x) * cc.x + sigf(gi.x) * tanh_f(gg.x);
    cn.y = sigf(gf.y) * cc.y + sigf(gi.y) * tanh_f(gg.y);
    cn.z = sigf(gf.z) * cc.z + sigf(gi.z) * tanh_f(gg.z);
    cn.w = sigf(gf.w) * cc.w + sigf(gi.w) * tanh_f(gg.w);
    hn.x = sigf(go.x) * tanh_f(cn.x);
    hn.y = sigf(go.y) * tanh_f(cn.y);
    hn.z = sigf(go.z) * tanh_f(cn.z);
    hn.w = sigf(go.w) * tanh_f(cn.w);
    *reinterpret_cast<float4*>(&s.cx[r][c]) = cn;
    *reinterpret_cast<float4*>(&s.hx[r][c]) = hn;
  }
  __syncwarp();
}

__global__ void __launch_bounds__(NT, 1)
stgnn_kernel(const float* __restrict__ x, const float* __restrict__ adj,
             const float* __restrict__ Wenc_g, const float* __restrict__ benc_g,
             const float* __restrict__ Wg1_g, const float* __restrict__ bg1_g,
             const float* __restrict__ Wg2_g, const float* __restrict__ bg2_g,
             const float* __restrict__ Wih_g, const float* __restrict__ Whh_g,
             const float* __restrict__ bih_g, const float* __restrict__ bhh_g,
             const float* __restrict__ Wd1_g, const float* __restrict__ bd1_g,
             const float* __restrict__ Wd2_g, const float* __restrict__ bd2_g,
             float* __restrict__ out) {
  extern __shared__ __align__(16) unsigned char smem_raw[];
  Smem& s = *reinterpret_cast<Smem*>(smem_raw);
  const int tid = threadIdx.x;
  const int b = blockIdx.x;
  const int r = tid >> 3;
  const int j = tid & 7;

  // ---- one-time per-CTA setup ----
  for (int i = tid; i < INF * 64; i += NT) (&s.Wenc[0][0])[i] = Wenc_g[i];
  for (int i = tid; i < 64 * 64; i += NT) (&s.Wg1[0][0])[i] = Wg1_g[i];
  for (int i = tid; i < 64 * 64; i += NT) (&s.Wg2[0][0])[i] = Wg2_g[i];
  for (int i = tid; i < 64 * 32; i += NT) (&s.Wd1[0][0])[i] = Wd1_g[i];
  if (tid < 192) s.Wd2[tid / 6][tid % 6] = Wd2_g[tid];
  if (tid < 64) {
    s.benc[tid] = benc_g[tid];
    s.bg1[tid] = bg1_g[tid];
    s.bg2[tid] = bg2_g[tid];
  }
  if (tid < 32) s.bd1[tid] = bd1_g[tid];
  if (tid < 6) s.bd2[tid] = bd2_g[tid];
  if (tid < 32) {
    float sum = 0.f;
    for (int jj = 0; jj < 32; jj++)
      sum += (jj == tid) ? 1.f : adj[tid * 32 + jj];
    s.dvec[tid] = rsqrtf(fmaxf(sum, 1.f));
  }
  for (int i = tid; i < 32 * LDA; i += NT) {
    (&s.hx[0][0])[i] = 0.f;
    (&s.cx[0][0])[i] = 0.f;
  }
  __syncthreads();
  for (int i = tid; i < 32 * 32; i += NT) {
    int ii = i >> 5, jj = i & 31;
    float a = (ii == jj) ? 1.f : adj[i];
    s.Ahat[ii][jj] = s.dvec[ii] * a * s.dvec[jj];
  }

  // LSTM weights: thread tid owns gate column tid -> 64 packed (b64) regs
  p2 wih[32], whh[32];
  {
    const ulonglong2* p = reinterpret_cast<const ulonglong2*>(Wih_g + tid * 64);
    const ulonglong2* q = reinterpret_cast<const ulonglong2*>(Whh_g + tid * 64);
#pragma unroll
    for (int i = 0; i < 16; i++) {
      ulonglong2 v = p[i];
      wih[2 * i] = v.x; wih[2 * i + 1] = v.y;
      ulonglong2 u = q[i];
      whh[2 * i] = u.x; whh[2 * i + 1] = u.y;
    }
  }
  const float bb = bih_g[tid] + bhh_g[tid];
  __syncthreads();

  // ---- encoder: 48 steps ----
  for (int t = 0; t < TT; t++) {
    const float* xt = x + ((size_t)b * TT + t) * (NNODE * INF);
    // row-local frame load: writers == readers' warp -> syncwarp suffices
    s.xbuf[r][j] = xt[r * INF + j];
    if (j < 3) s.xbuf[r][j + 8] = xt[r * INF + j + 8];
    __syncwarp();
    step_common(s, wih, whh, bb, tid);
  }

  // ---- decoder: 48 steps (xbuf currently holds last frame = pred|stat) ----
  for (int f = 0; f < FUT; f++) {
    step_common(s, wih, whh, bb, tid);
    // h1 = relu(hx @ W_d1 + b_d1)  (reads hx[r]: row-local, post step syncwarp)
    rowmm<64, 32, 4, true, true>(&s.hx[r][0], &s.Wd1[0][0], s.bd1,
                                 &s.h1[r][0], j * 4);
    __syncthreads();
    // res = h1 @ W_d2 + b_d2 ; pred += res ; emit
    if (tid < 192) {
      int rr = tid / 6, d = tid - rr * 6;
      float acc = s.bd2[d];
#pragma unroll
      for (int k = 0; k < 32; k++) acc += s.h1[rr][k] * s.Wd2[k][d];
      float p = s.xbuf[rr][d] + acc;
      s.xbuf[rr][d] = p;
      out[(((size_t)b * FUT + f) * NNODE + rr) * 6 + d] = p;
    }
    __syncthreads();
  }
}

extern "C" void kernel_launch(void* const* d_in, const int* in_sizes, int n_in,
                              void* d_out, int out_size) {
  const float* x    = (const float*)d_in[0];
  const float* adj  = (const float*)d_in[1];
  const float* Wenc = (const float*)d_in[2];
  const float* benc = (const float*)d_in[3];
  const float* Wg1  = (const float*)d_in[4];
  const float* bg1  = (const float*)d_in[5];
  const float* Wg2  = (const float*)d_in[6];
  const float* bg2  = (const float*)d_in[7];
  const float* Wih  = (const float*)d_in[8];
  const float* Whh  = (const float*)d_in[9];
  const float* bih  = (const float*)d_in[10];
  const float* bhh  = (const float*)d_in[11];
  const float* Wd1  = (const float*)d_in[12];
  const float* bd1  = (const float*)d_in[13];
  const float* Wd2  = (const float*)d_in[14];
  const float* bd2  = (const float*)d_in[15];
  float* out = (float*)d_out;

  int B = in_sizes[0] / (TT * NNODE * INF);

  cudaFuncSetAttribute(stgnn_kernel,
                       cudaFuncAttributeMaxDynamicSharedMemorySize,
                       (int)sizeof(Smem));
  stgnn_kernel<<<B, NT, sizeof(Smem)>>>(x, adj, Wenc, benc, Wg1, bg1, Wg2, bg2,
                                        Wih, Whh, bih, bhh, Wd1, bd1, Wd2, bd2,
                                        out);
}

// round 5
// speedup vs baseline: 1.4029x; 1.3934x over previous
#include <cuda_runtime.h>

#define NT 256          // threads per CTA
#define TT 48           // encoder timesteps
#define FUT 48          // decoder steps
#define NNODE 32
#define INF 11
#define LDA 68          // padded activation row stride (floats)
#define LDZ 132         // zbuf row stride: [xf(64) | hx(64)] + pad
#define LDGR 260        // padded g row stride (floats)

// ---------------------------------------------------------------------------
// packed fp32x2 carried as b64
// ---------------------------------------------------------------------------
typedef unsigned long long p2;

__device__ __forceinline__ p2 ffma2p(p2 a, p2 b, p2 c) {
  p2 d;
  asm("fma.rn.f32x2 %0, %1, %2, %3;" : "=l"(d) : "l"(a), "l"(b), "l"(c));
  return d;
}
__device__ __forceinline__ p2 add2p(p2 a, p2 b) {
  p2 d;
  asm("add.rn.f32x2 %0, %1, %2;" : "=l"(d) : "l"(a), "l"(b));
  return d;
}
__device__ __forceinline__ p2 pack2(float lo, float hi) {
  p2 d;
  asm("mov.b64 %0, {%1, %2};" : "=l"(d) : "f"(lo), "f"(hi));
  return d;
}
__device__ __forceinline__ float2 up2(p2 a) {
  float2 f;
  asm("mov.b64 {%0, %1}, %2;" : "=f"(f.x), "=f"(f.y) : "l"(a));
  return f;
}

__device__ __forceinline__ float sigf(float x) {
  return __fdividef(1.0f, 1.0f + __expf(-x));
}
__device__ __forceinline__ float tanh_f(float x) {
  return __fdividef(2.0f, 1.0f + __expf(-2.0f * x)) - 1.0f;
}

struct __align__(16) Smem {
  float Ahat[32][36];
  float Wenc[11][64];
  float Wg1[64][64];
  float Wg2[64][64];
  float Wd1[64][32];
  float Wd2[32][8];
  float benc[64];
  float bg1[64];
  float bg2[64];
  float bd1[32];
  float bd2[8];
  float dvec[32];
  float xbuf[32][12];     // current input frame
  float act0[32][LDA];    // enc / tmp2
  float act1[32][LDA];    // tmp
  float act2[32][LDA];    // s1
  float zbuf[32][LDZ];    // [xf | hx] per row, contiguous for LSTM stream
  float g[32][LDGR];      // LSTM pre-activations
  float h1[32][36];       // decoder hidden
};

// Computes output cols {4j..4j+3} and (TWOBLK) {32+4j..32+4j+3} for row r.
// Lane layout: the 8 lanes of a row-group load 128B CONTIGUOUS per k
// (1 wavefront), and the 4 row-groups of a warp read identical addresses
// (broadcast dedup).
template<int K, int LDW, bool BIAS, bool RELU, bool TWOBLK>
__device__ __forceinline__ void rowmm2(const float* __restrict__ A,
                                       const float* __restrict__ W,
                                       const float* __restrict__ bias,
                                       float* __restrict__ outp, int j) {
  const int ca = 4 * j;
  const int cb = 32 + 4 * j;
  p2 acc0, acc1, acc2, acc3;
  if (BIAS) {
    ulonglong2 b0 = *reinterpret_cast<const ulonglong2*>(bias + ca);
    acc0 = b0.x; acc1 = b0.y;
    if (TWOBLK) {
      ulonglong2 b1 = *reinterpret_cast<const ulonglong2*>(bias + cb);
      acc2 = b1.x; acc3 = b1.y;
    } else { acc2 = 0ull; acc3 = 0ull; }
  } else {
    acc0 = acc1 = acc2 = acc3 = 0ull;
  }
#pragma unroll
  for (int k = 0; k < K; k++) {
    float av = A[k];
    p2 aa = pack2(av, av);
    ulonglong2 w0 = *reinterpret_cast<const ulonglong2*>(W + k * LDW + ca);
    acc0 = ffma2p(aa, w0.x, acc0);
    acc1 = ffma2p(aa, w0.y, acc1);
    if (TWOBLK) {
      ulonglong2 w1 = *reinterpret_cast<const ulonglong2*>(W + k * LDW + cb);
      acc2 = ffma2p(aa, w1.x, acc2);
      acc3 = ffma2p(aa, w1.y, acc3);
    }
  }
  float2 f0 = up2(acc0), f1 = up2(acc1);
  float4 o0;
  o0.x = RELU ? fmaxf(f0.x, 0.f) : f0.x;
  o0.y = RELU ? fmaxf(f0.y, 0.f) : f0.y;
  o0.z = RELU ? fmaxf(f1.x, 0.f) : f1.x;
  o0.w = RELU ? fmaxf(f1.y, 0.f) : f1.y;
  *reinterpret_cast<float4*>(outp + ca) = o0;
  if (TWOBLK) {
    float2 f2 = up2(acc2), f3 = up2(acc3);
    float4 o1;
    o1.x = RELU ? fmaxf(f2.x, 0.f) : f2.x;
    o1.y = RELU ? fmaxf(f2.y, 0.f) : f2.y;
    o1.z = RELU ? fmaxf(f3.x, 0.f) : f3.x;
    o1.w = RELU ? fmaxf(f3.y, 0.f) : f3.y;
    *reinterpret_cast<float4*>(outp + cb) = o1;
  }
}

// GCN (2 layers) + LSTM step. wcat = concat(W_ih[tid], W_hh[tid]) packed,
// register resident. cx lives in the owner thread's registers (cx0, cx1).
// Thread tid: r = tid>>3 (row), j = tid&7; owns h-units {4j..4j+3} and
// {32+4j..32+4j+3} of row r for the gate update.
__device__ __forceinline__ void step_common(Smem& s, const p2* wcat, float bb,
                                            float4& cx0, float4& cx1,
                                            int tid) {
  const int r = tid >> 3;
  const int j = tid & 7;

  // enc = relu(x @ W_enc + b_enc)                       (row-local consumers)
  rowmm2<INF, 64, true, true, true>(&s.xbuf[r][0], &s.Wenc[0][0], s.benc,
                                    &s.act0[r][0], j);
  __syncwarp();
  // tmp = enc @ W_g1                                    (all-to-all)
  rowmm2<64, 64, false, false, true>(&s.act0[r][0], &s.Wg1[0][0], nullptr,
                                     &s.act1[r][0], j);
  __syncthreads();
  // s1 = relu(Ahat @ tmp + b_g1)                        (row-local)
  rowmm2<32, LDA, true, true, true>(&s.Ahat[r][0], &s.act1[0][0], s.bg1,
                                    &s.act2[r][0], j);
  __syncwarp();
  // tmp2 = s1 @ W_g2                                    (all-to-all)
  rowmm2<64, 64, false, false, true>(&s.act2[r][0], &s.Wg2[0][0], nullptr,
                                     &s.act0[r][0], j);
  __syncthreads();
  // xf = relu(Ahat @ tmp2 + b_g2) -> zbuf[.][0..64)     (all-to-all, LSTM)
  rowmm2<32, LDA, true, true, true>(&s.Ahat[r][0], &s.act0[0][0], s.bg2,
                                    &s.zbuf[r][0], j);
  __syncthreads();

  // LSTM: g[row][tid] = bb + z[row] . wcat   (z = [xf|hx], 128 floats)
  // 4 rows per block -> 8 independent accumulator chains.
#pragma unroll 1
  for (int rr = 0; rr < 32; rr += 4) {
    const ulonglong2* z0 = reinterpret_cast<const ulonglong2*>(&s.zbuf[rr][0]);
    const ulonglong2* z1 = reinterpret_cast<const ulonglong2*>(&s.zbuf[rr + 1][0]);
    const ulonglong2* z2 = reinterpret_cast<const ulonglong2*>(&s.zbuf[rr + 2][0]);
    const ulonglong2* z3 = reinterpret_cast<const ulonglong2*>(&s.zbuf[rr + 3][0]);
    p2 a0 = 0ull, a1 = 0ull, b0 = 0ull, b1 = 0ull;
    p2 c0 = 0ull, c1 = 0ull, d0 = 0ull, d1 = 0ull;
#pragma unroll
    for (int q = 0; q < 32; q++) {
      p2 wlo = wcat[2 * q], whi = wcat[2 * q + 1];
      ulonglong2 v0 = z0[q];
      a0 = ffma2p(v0.x, wlo, a0);
      a1 = ffma2p(v0.y, whi, a1);
      ulonglong2 v1 = z1[q];
      b0 = ffma2p(v1.x, wlo, b0);
      b1 = ffma2p(v1.y, whi, b1);
      ulonglong2 v2 = z2[q];
      c0 = ffma2p(v2.x, wlo, c0);
      c1 = ffma2p(v2.y, whi, c1);
      ulonglong2 v3 = z3[q];
      d0 = ffma2p(v3.x, wlo, d0);
      d1 = ffma2p(v3.y, whi, d1);
    }
    float2 fa = up2(add2p(a0, a1));
    s.g[rr][tid] = bb + fa.x + fa.y;
    float2 fb = up2(add2p(b0, b1));
    s.g[rr + 1][tid] = bb + fb.x + fb.y;
    float2 fc = up2(add2p(c0, c1));
    s.g[rr + 2][tid] = bb + fc.x + fc.y;
    float2 fd = up2(add2p(d0, d1));
    s.g[rr + 3][tid] = bb + fd.x + fd.y;
  }
  __syncthreads();

  // gate nonlinearity + state update; hx -> zbuf[r][64+u] (1-wf blocks)
#pragma unroll
  for (int h4 = 0; h4 < 2; h4++) {
    int base = h4 * 32 + 4 * j;
    float4 gi = *reinterpret_cast<const float4*>(&s.g[r][base]);
    float4 gf = *reinterpret_cast<const float4*>(&s.g[r][64 + base]);
    float4 gg = *reinterpret_cast<const float4*>(&s.g[r][128 + base]);
    float4 go = *reinterpret_cast<const float4*>(&s.g[r][192 + base]);
    float4 cc = h4 ? cx1 : cx0;
    float4 cn, hn;
    cn.x = sigf(gf.x) * cc.x + sigf(gi.x) * tanh_f(gg.x);
    cn.y = sigf(gf.y) * cc.y + sigf(gi.y) * tanh_f(gg.y);
    cn.z = sigf(gf.z) * cc.z + sigf(gi.z) * tanh_f(gg.z);
    cn.w = sigf(gf.w) * cc.w + sigf(gi.w) * tanh_f(gg.w);
    hn.x = sigf(go.x) * tanh_f(cn.x);
    hn.y = sigf(go.y) * tanh_f(cn.y);
    hn.z = sigf(go.z) * tanh_f(cn.z);
    hn.w = sigf(go.w) * tanh_f(cn.w);
    if (h4) cx1 = cn; else cx0 = cn;
    *reinterpret_cast<float4*>(&s.zbuf[r][64 + base]) = hn;
  }
  __syncwarp();
}

__global__ void __launch_bounds__(NT, 1)
stgnn_kernel(const float* __restrict__ x, const float* __restrict__ adj,
             const float* __restrict__ Wenc_g, const float* __restrict__ benc_g,
             const float* __restrict__ Wg1_g, const float* __restrict__ bg1_g,
             const float* __restrict__ Wg2_g, const float* __restrict__ bg2_g,
             const float* __restrict__ Wih_g, const float* __restrict__ Whh_g,
             const float* __restrict__ bih_g, const float* __restrict__ bhh_g,
             const float* __restrict__ Wd1_g, const float* __restrict__ bd1_g,
             const float* __restrict__ Wd2_g, const float* __restrict__ bd2_g,
             float* __restrict__ out) {
  extern __shared__ __align__(16) unsigned char smem_raw[];
  Smem& s = *reinterpret_cast<Smem*>(smem_raw);
  const int tid = threadIdx.x;
  const int b = blockIdx.x;
  const int r = tid >> 3;
  const int j = tid & 7;

  // ---- one-time per-CTA setup ----
  for (int i = tid; i < INF * 64; i += NT) (&s.Wenc[0][0])[i] = Wenc_g[i];
  for (int i = tid; i < 64 * 64; i += NT) (&s.Wg1[0][0])[i] = Wg1_g[i];
  for (int i = tid; i < 64 * 64; i += NT) (&s.Wg2[0][0])[i] = Wg2_g[i];
  for (int i = tid; i < 64 * 32; i += NT) (&s.Wd1[0][0])[i] = Wd1_g[i];
  if (tid < 192) s.Wd2[tid / 6][tid % 6] = Wd2_g[tid];
  if (tid < 64) {
    s.benc[tid] = benc_g[tid];
    s.bg1[tid] = bg1_g[tid];
    s.bg2[tid] = bg2_g[tid];
  }
  if (tid < 32) s.bd1[tid] = bd1_g[tid];
  if (tid < 6) s.bd2[tid] = bd2_g[tid];
  if (tid < 32) {
    float sum = 0.f;
    for (int jj = 0; jj < 32; jj++)
      sum += (jj == tid) ? 1.f : adj[tid * 32 + jj];
    s.dvec[tid] = rsqrtf(fmaxf(sum, 1.f));
  }
  for (int i = tid; i < 32 * LDZ; i += NT) (&s.zbuf[0][0])[i] = 0.f;
  __syncthreads();
  for (int i = tid; i < 32 * 32; i += NT) {
    int ii = i >> 5, jj = i & 31;
    float a = (ii == jj) ? 1.f : adj[i];
    s.Ahat[ii][jj] = s.dvec[ii] * a * s.dvec[jj];
  }

  // LSTM weights for gate column tid: wcat = [W_ih row | W_hh row] packed
  p2 wcat[64];
  {
    const ulonglong2* p = reinterpret_cast<const ulonglong2*>(Wih_g + tid * 64);
    const ulonglong2* q = reinterpret_cast<const ulonglong2*>(Whh_g + tid * 64);
#pragma unroll
    for (int i = 0; i < 16; i++) {
      ulonglong2 v = p[i];
      wcat[2 * i] = v.x; wcat[2 * i + 1] = v.y;
      ulonglong2 u = q[i];
      wcat[32 + 2 * i] = u.x; wcat[32 + 2 * i + 1] = u.y;
    }
  }
  const float bb = bih_g[tid] + bhh_g[tid];
  float4 cx0 = make_float4(0.f, 0.f, 0.f, 0.f);
  float4 cx1 = make_float4(0.f, 0.f, 0.f, 0.f);
  __syncthreads();

  // ---- encoder: 48 steps ----
  for (int t = 0; t < TT; t++) {
    const float* xt = x + ((size_t)b * TT + t) * (NNODE * INF);
    s.xbuf[r][j] = xt[r * INF + j];
    if (j < 3) s.xbuf[r][j + 8] = xt[r * INF + j + 8];
    __syncwarp();
    step_common(s, wcat, bb, cx0, cx1, tid);
  }

  // ---- decoder: 48 steps ----
  for (int f = 0; f < FUT; f++) {
    step_common(s, wcat, bb, cx0, cx1, tid);
    // h1 = relu(hx @ W_d1 + b_d1); hx row-local in zbuf[r][64..128)
    rowmm2<64, 32, true, true, false>(&s.zbuf[r][64], &s.Wd1[0][0], s.bd1,
                                      &s.h1[r][0], j);
    __syncthreads();
    // res = h1 @ W_d2 + b_d2 ; pred += res ; emit
    if (tid < 192) {
      int rr = tid / 6, d = tid - rr * 6;
      float acc = s.bd2[d];
#pragma unroll
      for (int k = 0; k < 32; k++) acc += s.h1[rr][k] * s.Wd2[k][d];
      float p = s.xbuf[rr][d] + acc;
      s.xbuf[rr][d] = p;
      out[(((size_t)b * FUT + f) * NNODE + rr) * 6 + d] = p;
    }
    __syncthreads();
  }
}

extern "C" void kernel_launch(void* const* d_in, const int* in_sizes, int n_in,
                              void* d_out, int out_size) {
  const float* x    = (const float*)d_in[0];
  const float* adj  = (const float*)d_in[1];
  const float* Wenc = (const float*)d_in[2];
  const float* benc = (const float*)d_in[3];
  const float* Wg1  = (const float*)d_in[4];
  const float* bg1  = (const float*)d_in[5];
  const float* Wg2  = (const float*)d_in[6];
  const float* bg2  = (const float*)d_in[7];
  const float* Wih  = (const float*)d_in[8];
  const float* Whh  = (const float*)d_in[9];
  const float* bih  = (const float*)d_in[10];
  const float* bhh  = (const float*)d_in[11];
  const float* Wd1  = (const float*)d_in[12];
  const float* bd1  = (const float*)d_in[13];
  const float* Wd2  = (const float*)d_in[14];
  const float* bd2  = (const float*)d_in[15];
  float* out = (float*)d_out;

  int B = in_sizes[0] / (TT * NNODE * INF);

  cudaFuncSetAttribute(stgnn_kernel,
                       cudaFuncAttributeMaxDynamicSharedMemorySize,
                       (int)sizeof(Smem));
  stgnn_kernel<<<B, NT, sizeof(Smem)>>>(x, adj, Wenc, benc, Wg1, bg1, Wg2, bg2,
                                        Wih, Whh, bih, bhh, Wd1, bd1, Wd2, bd2,
                                        out);
}

// round 6
// speedup vs baseline: 1.5695x; 1.1188x over previous
#include <cuda_runtime.h>

#define NT 256          // threads per CTA
#define TT 48           // encoder timesteps
#define FUT 48          // decoder steps
#define NNODE 32
#define INF 11
#define LDA 68          // padded activation row stride (floats)
#define LDZ 132         // zbuf row stride: [xf(64) | hx(64)] + pad
#define LDGR 260        // padded g row stride (floats)

// ---------------------------------------------------------------------------
// packed fp32x2 carried as b64
// ---------------------------------------------------------------------------
typedef unsigned long long p2;

__device__ __forceinline__ p2 ffma2p(p2 a, p2 b, p2 c) {
  p2 d;
  asm("fma.rn.f32x2 %0, %1, %2, %3;" : "=l"(d) : "l"(a), "l"(b), "l"(c));
  return d;
}
__device__ __forceinline__ p2 pack2(float lo, float hi) {
  p2 d;
  asm("mov.b64 %0, {%1, %2};" : "=l"(d) : "f"(lo), "f"(hi));
  return d;
}
__device__ __forceinline__ float2 up2(p2 a) {
  float2 f;
  asm("mov.b64 {%0, %1}, %2;" : "=f"(f.x), "=f"(f.y) : "l"(a));
  return f;
}
__device__ __forceinline__ float hadd2(p2 a) {
  float2 f = up2(a);
  return f.x + f.y;
}

__device__ __forceinline__ float sigf(float x) {
  return __fdividef(1.0f, 1.0f + __expf(-x));
}
__device__ __forceinline__ float tanh_f(float x) {
  return __fdividef(2.0f, 1.0f + __expf(-2.0f * x)) - 1.0f;
}

struct __align__(16) Smem {
  float Ahat[32][36];
  float Wenc[11][64];
  float Wg1[64][64];
  float Wg2[64][64];
  float Wd1[64][32];
  float Wd2[32][8];
  float benc[64];
  float bg1[64];
  float bg2[64];
  float bd1[32];
  float bd2[8];
  float dvec[32];
  float xbuf[32][12];     // current input frame
  float act0[32][LDA];    // enc / tmp2
  float act1[32][LDA];    // tmp
  float act2[32][LDA];    // s1
  float zbuf[32][LDZ];    // [xf | hx] per row, contiguous for LSTM stream
  float g[32][LDGR];      // LSTM pre-activations
  float h1[32][36];       // decoder hidden
};

// Computes output cols {4j..4j+3} and (TWOBLK) {32+4j..32+4j+3} for row r.
// 8 lanes of a row-group load 128B contiguous per k (1 wavefront); the 4
// row-groups of a warp read identical addresses (broadcast dedup).
template<int K, int LDW, bool BIAS, bool RELU, bool TWOBLK>
__device__ __forceinline__ void rowmm2(const float* __restrict__ A,
                                       const float* __restrict__ W,
                                       const float* __restrict__ bias,
                                       float* __restrict__ outp, int j) {
  const int ca = 4 * j;
  const int cb = 32 + 4 * j;
  p2 acc0, acc1, acc2, acc3;
  if (BIAS) {
    ulonglong2 b0 = *reinterpret_cast<const ulonglong2*>(bias + ca);
    acc0 = b0.x; acc1 = b0.y;
    if (TWOBLK) {
      ulonglong2 b1 = *reinterpret_cast<const ulonglong2*>(bias + cb);
      acc2 = b1.x; acc3 = b1.y;
    } else { acc2 = 0ull; acc3 = 0ull; }
  } else {
    acc0 = acc1 = acc2 = acc3 = 0ull;
  }
#pragma unroll
  for (int k = 0; k < K; k++) {
    float av = A[k];
    p2 aa = pack2(av, av);
    ulonglong2 w0 = *reinterpret_cast<const ulonglong2*>(W + k * LDW + ca);
    acc0 = ffma2p(aa, w0.x, acc0);
    acc1 = ffma2p(aa, w0.y, acc1);
    if (TWOBLK) {
      ulonglong2 w1 = *reinterpret_cast<const ulonglong2*>(W + k * LDW + cb);
      acc2 = ffma2p(aa, w1.x, acc2);
      acc3 = ffma2p(aa, w1.y, acc3);
    }
  }
  float2 f0 = up2(acc0), f1 = up2(acc1);
  float4 o0;
  o0.x = RELU ? fmaxf(f0.x, 0.f) : f0.x;
  o0.y = RELU ? fmaxf(f0.y, 0.f) : f0.y;
  o0.z = RELU ? fmaxf(f1.x, 0.f) : f1.x;
  o0.w = RELU ? fmaxf(f1.y, 0.f) : f1.y;
  *reinterpret_cast<float4*>(outp + ca) = o0;
  if (TWOBLK) {
    float2 f2 = up2(acc2), f3 = up2(acc3);
    float4 o1;
    o1.x = RELU ? fmaxf(f2.x, 0.f) : f2.x;
    o1.y = RELU ? fmaxf(f2.y, 0.f) : f2.y;
    o1.z = RELU ? fmaxf(f3.x, 0.f) : f3.x;
    o1.w = RELU ? fmaxf(f3.y, 0.f) : f3.y;
    *reinterpret_cast<float4*>(outp + cb) = o1;
  }
}

// GCN (2 layers) + LSTM step.
// LSTM work split: lane l of warp w has kc = l>>3 (k-quarter, 32 of 128 k)
// and cg = l&7 (column quad: cols colbase..colbase+3, colbase = 32w + 4cg).
// wk[cc][2i(+1)] = packed weight pairs for column colbase+cc, k-chunk
// lc = (i + 2*kc)&7 within the quarter (rotation -> conflict-free z loads).
// Partial dot products are reduced across the 4 kc-groups via shfl.xor.
__device__ __forceinline__ void step_common(Smem& s, const p2 wk[4][16],
                                            const float4& bb4,
                                            const int* zoff,
                                            float4& cx0, float4& cx1,
                                            int tid, int colbase, int lane) {
  const int r = tid >> 3;
  const int j = tid & 7;

  // enc = relu(x @ W_enc + b_enc)                       (row-local consumers)
  rowmm2<INF, 64, true, true, true>(&s.xbuf[r][0], &s.Wenc[0][0], s.benc,
                                    &s.act0[r][0], j);
  __syncwarp();
  // tmp = enc @ W_g1                                    (all-to-all)
  rowmm2<64, 64, false, false, true>(&s.act0[r][0], &s.Wg1[0][0], nullptr,
                                     &s.act1[r][0], j);
  __syncthreads();
  // s1 = relu(Ahat @ tmp + b_g1)                        (row-local)
  rowmm2<32, LDA, true, true, true>(&s.Ahat[r][0], &s.act1[0][0], s.bg1,
                                    &s.act2[r][0], j);
  __syncwarp();
  // tmp2 = s1 @ W_g2                                    (all-to-all)
  rowmm2<64, 64, false, false, true>(&s.act2[r][0], &s.Wg2[0][0], nullptr,
                                     &s.act0[r][0], j);
  __syncthreads();
  // xf = relu(Ahat @ tmp2 + b_g2) -> zbuf[.][0..64)     (all-to-all, LSTM)
  rowmm2<32, LDA, true, true, true>(&s.Ahat[r][0], &s.act0[0][0], s.bg2,
                                    &s.zbuf[r][0], j);
  __syncthreads();

  // LSTM: g[row][c] = bias + z[row] . W[:,c]   (z = [xf|hx], 128 floats)
  // Each thread: its k-quarter against its 4 columns; shfl-reduce over kc.
#pragma unroll 2
  for (int rr = 0; rr < 32; rr++) {
    const float* zr = &s.zbuf[rr][0];
    p2 a0 = 0ull, a1 = 0ull, a2 = 0ull, a3 = 0ull;
#pragma unroll
    for (int i = 0; i < 8; i++) {
      ulonglong2 zz = *reinterpret_cast<const ulonglong2*>(zr + zoff[i]);
      a0 = ffma2p(zz.x, wk[0][2 * i], a0);
      a1 = ffma2p(zz.x, wk[1][2 * i], a1);
      a2 = ffma2p(zz.x, wk[2][2 * i], a2);
      a3 = ffma2p(zz.x, wk[3][2 * i], a3);
      a0 = ffma2p(zz.y, wk[0][2 * i + 1], a0);
      a1 = ffma2p(zz.y, wk[1][2 * i + 1], a1);
      a2 = ffma2p(zz.y, wk[2][2 * i + 1], a2);
      a3 = ffma2p(zz.y, wk[3][2 * i + 1], a3);
    }
    float s0 = hadd2(a0), s1 = hadd2(a1), s2 = hadd2(a2), s3 = hadd2(a3);
    s0 += __shfl_xor_sync(0xffffffffu, s0, 8);
    s1 += __shfl_xor_sync(0xffffffffu, s1, 8);
    s2 += __shfl_xor_sync(0xffffffffu, s2, 8);
    s3 += __shfl_xor_sync(0xffffffffu, s3, 8);
    s0 += __shfl_xor_sync(0xffffffffu, s0, 16);
    s1 += __shfl_xor_sync(0xffffffffu, s1, 16);
    s2 += __shfl_xor_sync(0xffffffffu, s2, 16);
    s3 += __shfl_xor_sync(0xffffffffu, s3, 16);
    if (lane < 8) {
      float4 o;
      o.x = s0 + bb4.x; o.y = s1 + bb4.y; o.z = s2 + bb4.z; o.w = s3 + bb4.w;
      *reinterpret_cast<float4*>(&s.g[rr][colbase]) = o;
    }
  }
  __syncthreads();

  // gate nonlinearity + state update; hx -> zbuf[r][64+u]
#pragma unroll
  for (int h4 = 0; h4 < 2; h4++) {
    int base = h4 * 32 + 4 * j;
    float4 gi = *reinterpret_cast<const float4*>(&s.g[r][base]);
    float4 gf = *reinterpret_cast<const float4*>(&s.g[r][64 + base]);
    float4 gg = *reinterpret_cast<const float4*>(&s.g[r][128 + base]);
    float4 go = *reinterpret_cast<const float4*>(&s.g[r][192 + base]);
    float4 cc = h4 ? cx1 : cx0;
    float4 cn, hn;
    cn.x = sigf(gf.x) * cc.x + sigf(gi.x) * tanh_f(gg.x);
    cn.y = sigf(gf.y) * cc.y + sigf(gi.y) * tanh_f(gg.y);
    cn.z = sigf(gf.z) * cc.z + sigf(gi.z) * tanh_f(gg.z);
    cn.w = sigf(gf.w) * cc.w + sigf(gi.w) * tanh_f(gg.w);
    hn.x = sigf(go.x) * tanh_f(cn.x);
    hn.y = sigf(go.y) * tanh_f(cn.y);
    hn.z = sigf(go.z) * tanh_f(cn.z);
    hn.w = sigf(go.w) * tanh_f(cn.w);
    if (h4) cx1 = cn; else cx0 = cn;
    *reinterpret_cast<float4*>(&s.zbuf[r][64 + base]) = hn;
  }
  __syncwarp();
}

__global__ void __launch_bounds__(NT, 1)
stgnn_kernel(const float* __restrict__ x, const float* __restrict__ adj,
             const float* __restrict__ Wenc_g, const float* __restrict__ benc_g,
             const float* __restrict__ Wg1_g, const float* __restrict__ bg1_g,
             const float* __restrict__ Wg2_g, const float* __restrict__ bg2_g,
             const float* __restrict__ Wih_g, const float* __restrict__ Whh_g,
             const float* __restrict__ bih_g, const float* __restrict__ bhh_g,
             const float* __restrict__ Wd1_g, const float* __restrict__ bd1_g,
             const float* __restrict__ Wd2_g, const float* __restrict__ bd2_g,
             float* __restrict__ out) {
  extern __shared__ __align__(16) unsigned char smem_raw[];
  Smem& s = *reinterpret_cast<Smem*>(smem_raw);
  const int tid = threadIdx.x;
  const int b = blockIdx.x;
  const int r = tid >> 3;
  const int j = tid & 7;
  const int w = tid >> 5;
  const int lane = tid & 31;
  const int kc = lane >> 3;
  const int cg = lane & 7;
  const int colbase = 32 * w + 4 * cg;

  // ---- one-time per-CTA setup ----
  for (int i = tid; i < INF * 64; i += NT) (&s.Wenc[0][0])[i] = Wenc_g[i];
  for (int i = tid; i < 64 * 64; i += NT) (&s.Wg1[0][0])[i] = Wg1_g[i];
  for (int i = tid; i < 64 * 64; i += NT) (&s.Wg2[0][0])[i] = Wg2_g[i];
  for (int i = tid; i < 64 * 32; i += NT) (&s.Wd1[0][0])[i] = Wd1_g[i];
  if (tid < 192) s.Wd2[tid / 6][tid % 6] = Wd2_g[tid];
  if (tid < 64) {
    s.benc[tid] = benc_g[tid];
    s.bg1[tid] = bg1_g[tid];
    s.bg2[tid] = bg2_g[tid];
  }
  if (tid < 32) s.bd1[tid] = bd1_g[tid];
  if (tid < 6) s.bd2[tid] = bd2_g[tid];
  if (tid < 32) {
    float sum = 0.f;
    for (int jj = 0; jj < 32; jj++)
      sum += (jj == tid) ? 1.f : adj[tid * 32 + jj];
    s.dvec[tid] = rsqrtf(fmaxf(sum, 1.f));
  }
  for (int i = tid; i < 32 * LDZ; i += NT) (&s.zbuf[0][0])[i] = 0.f;
  __syncthreads();
  for (int i = tid; i < 32 * 32; i += NT) {
    int ii = i >> 5, jj = i & 31;
    float a = (ii == jj) ? 1.f : adj[i];
    s.Ahat[ii][jj] = s.dvec[ii] * a * s.dvec[jj];
  }

  // LSTM weights: 4 columns x 32-k quarter, rotation baked into layout.
  // Full k-vector for col c: k<64 -> W_ih[c][k], else W_hh[c][k-64].
  p2 wk[4][16];
  float4 bb4;
  int zoff[8];
#pragma unroll
  for (int i = 0; i < 8; i++) {
    int lc = (i + 2 * kc) & 7;
    zoff[i] = kc * 32 + lc * 4;
  }
  {
    const float* base =
        (kc < 2) ? (Wih_g + (size_t)kc * 32) : (Whh_g + (size_t)(kc - 2) * 32);
    float bbv[4];
#pragma unroll
    for (int cc = 0; cc < 4; cc++) {
      int c = colbase + cc;
      bbv[cc] = bih_g[c] + bhh_g[c];
      const float* src = base + (size_t)c * 64;
#pragma unroll
      for (int i = 0; i < 8; i++) {
        int lc = (i + 2 * kc) & 7;
        wk[cc][2 * i]     = pack2(src[lc * 4],     src[lc * 4 + 1]);
        wk[cc][2 * i + 1] = pack2(src[lc * 4 + 2], src[lc * 4 + 3]);
      }
    }
    bb4 = make_float4(bbv[0], bbv[1], bbv[2], bbv[3]);
  }
  float4 cx0 = make_float4(0.f, 0.f, 0.f, 0.f);
  float4 cx1 = make_float4(0.f, 0.f, 0.f, 0.f);
  __syncthreads();

  // ---- encoder: 48 steps ----
  for (int t = 0; t < TT; t++) {
    const float* xt = x + ((size_t)b * TT + t) * (NNODE * INF);
    s.xbuf[r][j] = xt[r * INF + j];
    if (j < 3) s.xbuf[r][j + 8] = xt[r * INF + j + 8];
    __syncwarp();
    step_common(s, wk, bb4, zoff, cx0, cx1, tid, colbase, lane);
  }

  // ---- decoder: 48 steps ----
  for (int f = 0; f < FUT; f++) {
    step_common(s, wk, bb4, zoff, cx0, cx1, tid, colbase, lane);
    // h1 = relu(hx @ W_d1 + b_d1); hx row-local in zbuf[r][64..128)
    rowmm2<64, 32, true, true, false>(&s.zbuf[r][64], &s.Wd1[0][0], s.bd1,
                                      &s.h1[r][0], j);
    __syncthreads();
    // res = h1 @ W_d2 + b_d2 ; pred += res ; emit
    if (tid < 192) {
      int rr = tid / 6, d = tid - rr * 6;
      float acc = s.bd2[d];
#pragma unroll
      for (int k = 0; k < 32; k++) acc += s.h1[rr][k] * s.Wd2[k][d];
      float p = s.xbuf[rr][d] + acc;
      s.xbuf[rr][d] = p;
      out[(((size_t)b * FUT + f) * NNODE + rr) * 6 + d] = p;
    }
    __syncthreads();
  }
}

extern "C" void kernel_launch(void* const* d_in, const int* in_sizes, int n_in,
                              void* d_out, int out_size) {
  const float* x    = (const float*)d_in[0];
  const float* adj  = (const float*)d_in[1];
  const float* Wenc = (const float*)d_in[2];
  const float* benc = (const float*)d_in[3];
  const float* Wg1  = (const float*)d_in[4];
  const float* bg1  = (const float*)d_in[5];
  const float* Wg2  = (const float*)d_in[6];
  const float* bg2  = (const float*)d_in[7];
  const float* Wih  = (const float*)d_in[8];
  const float* Whh  = (const float*)d_in[9];
  const float* bih  = (const float*)d_in[10];
  const float* bhh  = (const float*)d_in[11];
  const float* Wd1  = (const float*)d_in[12];
  const float* bd1  = (const float*)d_in[13];
  const float* Wd2  = (const float*)d_in[14];
  const float* bd2  = (const float*)d_in[15];
  float* out = (float*)d_out;

  int B = in_sizes[0] / (TT * NNODE * INF);

  cudaFuncSetAttribute(stgnn_kernel,
                       cudaFuncAttributeMaxDynamicSharedMemorySize,
                       (int)sizeof(Smem));
  stgnn_kernel<<<B, NT, sizeof(Smem)>>>(x, adj, Wenc, benc, Wg1, bg1, Wg2, bg2,
                                        Wih, Whh, bih, bhh, Wd1, bd1, Wd2, bd2,
                                        out);
}

// round 7
// speedup vs baseline: 1.9676x; 1.2537x over previous
#include <cuda_runtime.h>

#define NT 256          // threads per CTA
#define TT 48           // encoder timesteps
#define FUT 48          // decoder steps
#define NNODE 32
#define INF 11
#define LDA 68          // padded activation row stride (floats)
#define LDZ 132         // zbuf row stride: [s1/xf(64) | hx(64)] + pad
#define LDGR 260        // padded g row stride (floats)

// ---------------------------------------------------------------------------
// packed fp32x2 carried as b64
// ---------------------------------------------------------------------------
typedef unsigned long long p2;

__device__ __forceinline__ p2 ffma2p(p2 a, p2 b, p2 c) {
  p2 d;
  asm("fma.rn.f32x2 %0, %1, %2, %3;" : "=l"(d) : "l"(a), "l"(b), "l"(c));
  return d;
}
__device__ __forceinline__ p2 pack2(float lo, float hi) {
  p2 d;
  asm("mov.b64 %0, {%1, %2};" : "=l"(d) : "f"(lo), "f"(hi));
  return d;
}
__device__ __forceinline__ float2 up2(p2 a) {
  float2 f;
  asm("mov.b64 {%0, %1}, %2;" : "=f"(f.x), "=f"(f.y) : "l"(a));
  return f;
}
__device__ __forceinline__ float hadd2(p2 a) {
  float2 f = up2(a);
  return f.x + f.y;
}

__device__ __forceinline__ float sigf(float x) {
  return __fdividef(1.0f, 1.0f + __expf(-x));
}
__device__ __forceinline__ float tanh_f(float x) {
  return __fdividef(2.0f, 1.0f + __expf(-2.0f * x)) - 1.0f;
}

struct __align__(16) Smem {
  float Ahat[32][36];
  float Wenc[11][64];
  float Wg1[64][64];
  float Wg2[64][64];
  float Wd1[64][32];
  float Wd2[32][8];
  float benc[64];
  float bg1[64];
  float bg2[64];
  float bd1[32];
  float bd2[8];
  float dvec[32];
  float xbuf[2][32][12];   // current input frame per batch
  float act0[2][32][LDA];  // enc / tmp2
  float act1[2][32][LDA];  // tmp
  float zbuf[2][32][LDZ];  // [s1->xf | hx] per row
  float g[2][32][LDGR];    // LSTM pre-activations
  float h1[2][32][36];     // decoder hidden
};

__device__ __forceinline__ void relu4_store(p2 a0, p2 a1, bool relu,
                                            float* outp) {
  float2 f0 = up2(a0), f1 = up2(a1);
  float4 o;
  o.x = relu ? fmaxf(f0.x, 0.f) : f0.x;
  o.y = relu ? fmaxf(f0.y, 0.f) : f0.y;
  o.z = relu ? fmaxf(f1.x, 0.f) : f1.x;
  o.w = relu ? fmaxf(f1.y, 0.f) : f1.y;
  *reinterpret_cast<float4*>(outp) = o;
}

// Two-batch rowmm: output cols {4j..4j+3} (+TWOBLK {32+4j..}) of row r for
// BOTH batches, sharing all weight loads. Weight rows LDW-strided.
template<int K, int LDW, bool BIAS, bool RELU, bool TWOBLK>
__device__ __forceinline__ void rowmm2x2(const float* __restrict__ A0,
                                         const float* __restrict__ A1,
                                         const float* __restrict__ W,
                                         const float* __restrict__ bias,
                                         float* __restrict__ out0,
                                         float* __restrict__ out1, int j) {
  const int ca = 4 * j;
  const int cb = 32 + 4 * j;
  p2 x0, x1, x2, x3, y0, y1, y2, y3;
  if (BIAS) {
    ulonglong2 b0 = *reinterpret_cast<const ulonglong2*>(bias + ca);
    x0 = b0.x; x1 = b0.y; y0 = b0.x; y1 = b0.y;
    if (TWOBLK) {
      ulonglong2 b1 = *reinterpret_cast<const ulonglong2*>(bias + cb);
      x2 = b1.x; x3 = b1.y; y2 = b1.x; y3 = b1.y;
    } else { x2 = x3 = y2 = y3 = 0ull; }
  } else {
    x0 = x1 = x2 = x3 = y0 = y1 = y2 = y3 = 0ull;
  }
#pragma unroll
  for (int k = 0; k < K; k++) {
    float av0 = A0[k], av1 = A1[k];
    p2 aa0 = pack2(av0, av0);
    p2 aa1 = pack2(av1, av1);
    ulonglong2 w0 = *reinterpret_cast<const ulonglong2*>(W + k * LDW + ca);
    x0 = ffma2p(aa0, w0.x, x0);
    x1 = ffma2p(aa0, w0.y, x1);
    y0 = ffma2p(aa1, w0.x, y0);
    y1 = ffma2p(aa1, w0.y, y1);
    if (TWOBLK) {
      ulonglong2 w1 = *reinterpret_cast<const ulonglong2*>(W + k * LDW + cb);
      x2 = ffma2p(aa0, w1.x, x2);
      x3 = ffma2p(aa0, w1.y, x3);
      y2 = ffma2p(aa1, w1.x, y2);
      y3 = ffma2p(aa1, w1.y, y3);
    }
  }
  relu4_store(x0, x1, RELU, out0 + ca);
  relu4_store(y0, y1, RELU, out1 + ca);
  if (TWOBLK) {
    relu4_store(x2, x3, RELU, out0 + cb);
    relu4_store(y2, y3, RELU, out1 + cb);
  }
}

// GCN (2 layers) + LSTM for BOTH batches. LSTM split as R6 (lane = kc x cg,
// 4 cols x 32-k quarter, wk register resident, shfl reduce over kc), with
// the z-stream of both batches run against the same weights.
__device__ __forceinline__ void step_pair(Smem& s, const p2 wk[4][16],
                                          const float4& bb4, const int* zoff,
                                          float4& c00, float4& c01,
                                          float4& c10, float4& c11,
                                          int tid, int colbase, int lane) {
  const int r = tid >> 3;
  const int j = tid & 7;

  // enc = relu(x @ W_enc + b_enc)                      (row-local consumers)
  rowmm2x2<INF, 64, true, true, true>(&s.xbuf[0][r][0], &s.xbuf[1][r][0],
                                      &s.Wenc[0][0], s.benc,
                                      &s.act0[0][r][0], &s.act0[1][r][0], j);
  __syncwarp();
  // tmp = enc @ W_g1                                   (all-to-all consumer)
  rowmm2x2<64, 64, false, false, true>(&s.act0[0][r][0], &s.act0[1][r][0],
                                       &s.Wg1[0][0], nullptr,
                                       &s.act1[0][r][0], &s.act1[1][r][0], j);
  __syncthreads();
  // s1 = relu(Ahat @ tmp + b_g1) -> zbuf xf-slot       (row-local consumer)
  rowmm2x2<32, LDA, true, true, true>(&s.Ahat[r][0], &s.Ahat[r][0],
                                      &s.act1[0][0][0], s.bg1,  // W differs!
                                      &s.zbuf[0][r][0], &s.zbuf[1][r][0], j);
  // NOTE: the call above must use different W per batch; handled below.
  __syncwarp();
  // (placeholder — real s1 computed in specialized code below)
  __syncthreads();
}

// The Ahat-GEMMs have batch-dependent W (tmp arrays), so they get their own
// two-batch routine: A (Ahat row) is shared, W streams differ per batch.
template<bool RELU>
__device__ __forceinline__ void ahatmm_x2(const float* __restrict__ Arow,
                                          const float* __restrict__ W0,
                                          const float* __restrict__ W1,
                                          const float* __restrict__ bias,
                                          float* __restrict__ out0,
                                          float* __restrict__ out1, int j) {
  const int ca = 4 * j;
  const int cb = 32 + 4 * j;
  p2 x0, x1, x2, x3, y0, y1, y2, y3;
  ulonglong2 b0 = *reinterpret_cast<const ulonglong2*>(bias + ca);
  ulonglong2 b1 = *reinterpret_cast<const ulonglong2*>(bias + cb);
  x0 = b0.x; x1 = b0.y; y0 = b0.x; y1 = b0.y;
  x2 = b1.x; x3 = b1.y; y2 = b1.x; y3 = b1.y;
#pragma unroll
  for (int k = 0; k < 32; k++) {
    float av = Arow[k];
    p2 aa = pack2(av, av);
    ulonglong2 wa = *reinterpret_cast<const ulonglong2*>(W0 + k * LDA + ca);
    ulonglong2 wb = *reinterpret_cast<const ulonglong2*>(W0 + k * LDA + cb);
    x0 = ffma2p(aa, wa.x, x0);
    x1 = ffma2p(aa, wa.y, x1);
    x2 = ffma2p(aa, wb.x, x2);
    x3 = ffma2p(aa, wb.y, x3);
    ulonglong2 wc = *reinterpret_cast<const ulonglong2*>(W1 + k * LDA + ca);
    ulonglong2 wd = *reinterpret_cast<const ulonglong2*>(W1 + k * LDA + cb);
    y0 = ffma2p(aa, wc.x, y0);
    y1 = ffma2p(aa, wc.y, y1);
    y2 = ffma2p(aa, wd.x, y2);
    y3 = ffma2p(aa, wd.y, y3);
  }
  relu4_store(x0, x1, RELU, out0 + ca);
  relu4_store(x2, x3, RELU, out0 + cb);
  relu4_store(y0, y1, RELU, out1 + ca);
  relu4_store(y2, y3, RELU, out1 + cb);
}

// Full two-batch step (GCN + LSTM + gates).
__device__ __forceinline__ void step2(Smem& s, const p2 wk[4][16],
                                      const float4& bb4, const int* zoff,
                                      float4& c00, float4& c01,
                                      float4& c10, float4& c11,
                                      int tid, int colbase, int lane) {
  const int r = tid >> 3;
  const int j = tid & 7;

  // enc = relu(x @ W_enc + b_enc)
  rowmm2x2<INF, 64, true, true, true>(&s.xbuf[0][r][0], &s.xbuf[1][r][0],
                                      &s.Wenc[0][0], s.benc,
                                      &s.act0[0][r][0], &s.act0[1][r][0], j);
  __syncwarp();
  // tmp = enc @ W_g1
  rowmm2x2<64, 64, false, false, true>(&s.act0[0][r][0], &s.act0[1][r][0],
                                       &s.Wg1[0][0], nullptr,
                                       &s.act1[0][r][0], &s.act1[1][r][0], j);
  __syncthreads();
  // s1 = relu(Ahat @ tmp + b_g1) -> zbuf xf-slot (row-local consumer: tmp2)
  ahatmm_x2<true>(&s.Ahat[r][0], &s.act1[0][0][0], &s.act1[1][0][0], s.bg1,
                  &s.zbuf[0][r][0], &s.zbuf[1][r][0], j);
  __syncwarp();
  // tmp2 = s1 @ W_g2  (s1 read row-locally from zbuf xf-slot)
  rowmm2x2<64, 64, false, false, true>(&s.zbuf[0][r][0], &s.zbuf[1][r][0],
                                       &s.Wg2[0][0], nullptr,
                                       &s.act0[0][r][0], &s.act0[1][r][0], j);
  __syncthreads();
  // xf = relu(Ahat @ tmp2 + b_g2) -> zbuf xf-slot (s1 dead)
  ahatmm_x2<true>(&s.Ahat[r][0], &s.act0[0][0][0], &s.act0[1][0][0], s.bg2,
                  &s.zbuf[0][r][0], &s.zbuf[1][r][0], j);
  __syncthreads();

  // LSTM both batches: g[bat][row][c] = bias + z[bat][row] . W[:,c]
#pragma unroll 2
  for (int rr = 0; rr < 32; rr++) {
    const float* zr0 = &s.zbuf[0][rr][0];
    const float* zr1 = &s.zbuf[1][rr][0];
    p2 a0 = 0ull, a1 = 0ull, a2 = 0ull, a3 = 0ull;
    p2 e0 = 0ull, e1 = 0ull, e2 = 0ull, e3 = 0ull;
#pragma unroll
    for (int i = 0; i < 8; i++) {
      ulonglong2 z0 = *reinterpret_cast<const ulonglong2*>(zr0 + zoff[i]);
      ulonglong2 z1 = *reinterpret_cast<const ulonglong2*>(zr1 + zoff[i]);
      p2 wlo0 = wk[0][2 * i], whi0 = wk[0][2 * i + 1];
      p2 wlo1 = wk[1][2 * i], whi1 = wk[1][2 * i + 1];
      p2 wlo2 = wk[2][2 * i], whi2 = wk[2][2 * i + 1];
      p2 wlo3 = wk[3][2 * i], whi3 = wk[3][2 * i + 1];
      a0 = ffma2p(z0.x, wlo0, a0); a0 = ffma2p(z0.y, whi0, a0);
      a1 = ffma2p(z0.x, wlo1, a1); a1 = ffma2p(z0.y, whi1, a1);
      a2 = ffma2p(z0.x, wlo2, a2); a2 = ffma2p(z0.y, whi2, a2);
      a3 = ffma2p(z0.x, wlo3, a3); a3 = ffma2p(z0.y, whi3, a3);
      e0 = ffma2p(z1.x, wlo0, e0); e0 = ffma2p(z1.y, whi0, e0);
      e1 = ffma2p(z1.x, wlo1, e1); e1 = ffma2p(z1.y, whi1, e1);
      e2 = ffma2p(z1.x, wlo2, e2); e2 = ffma2p(z1.y, whi2, e2);
      e3 = ffma2p(z1.x, wlo3, e3); e3 = ffma2p(z1.y, whi3, e3);
    }
    float s0 = hadd2(a0), s1v = hadd2(a1), s2 = hadd2(a2), s3 = hadd2(a3);
    float t0 = hadd2(e0), t1 = hadd2(e1), t2 = hadd2(e2), t3 = hadd2(e3);
    s0 += __shfl_xor_sync(0xffffffffu, s0, 8);
    s1v += __shfl_xor_sync(0xffffffffu, s1v, 8);
    s2 += __shfl_xor_sync(0xffffffffu, s2, 8);
    s3 += __shfl_xor_sync(0xffffffffu, s3, 8);
    t0 += __shfl_xor_sync(0xffffffffu, t0, 8);
    t1 += __shfl_xor_sync(0xffffffffu, t1, 8);
    t2 += __shfl_xor_sync(0xffffffffu, t2, 8);
    t3 += __shfl_xor_sync(0xffffffffu, t3, 8);
    s0 += __shfl_xor_sync(0xffffffffu, s0, 16);
    s1v += __shfl_xor_sync(0xffffffffu, s1v, 16);
    s2 += __shfl_xor_sync(0xffffffffu, s2, 16);
    s3 += __shfl_xor_sync(0xffffffffu, s3, 16);
    t0 += __shfl_xor_sync(0xffffffffu, t0, 16);
    t1 += __shfl_xor_sync(0xffffffffu, t1, 16);
    t2 += __shfl_xor_sync(0xffffffffu, t2, 16);
    t3 += __shfl_xor_sync(0xffffffffu, t3, 16);
    if (lane < 8) {
      float4 o0, o1;
      o0.x = s0 + bb4.x; o0.y = s1v + bb4.y;
      o0.z = s2 + bb4.z; o0.w = s3 + bb4.w;
      o1.x = t0 + bb4.x; o1.y = t1 + bb4.y;
      o1.z = t2 + bb4.z; o1.w = t3 + bb4.w;
      *reinterpret_cast<float4*>(&s.g[0][rr][colbase]) = o0;
      *reinterpret_cast<float4*>(&s.g[1][rr][colbase]) = o1;
    }
  }
  __syncthreads();

  // gate nonlinearity + state update (both batches)
#pragma unroll
  for (int sel = 0; sel < 4; sel++) {
    int bat = sel >> 1;
    int h4 = sel & 1;
    int base = h4 * 32 + 4 * j;
    float4 gi = *reinterpret_cast<const float4*>(&s.g[bat][r][base]);
    float4 gf = *reinterpret_cast<const float4*>(&s.g[bat][r][64 + base]);
    float4 gg = *reinterpret_cast<const float4*>(&s.g[bat][r][128 + base]);
    float4 go = *reinterpret_cast<const float4*>(&s.g[bat][r][192 + base]);
    float4 cc = (sel == 0) ? c00 : (sel == 1) ? c01 : (sel == 2) ? c10 : c11;
    float4 cn, hn;
    cn.x = sigf(gf.x) * cc.x + sigf(gi.x) * tanh_f(gg.x);
    cn.y = sigf(gf.y) * cc.y + sigf(gi.y) * tanh_f(gg.y);
    cn.z = sigf(gf.z) * cc.z + sigf(gi.z) * tanh_f(gg.z);
    cn.w = sigf(gf.w) * cc.w + sigf(gi.w) * tanh_f(gg.w);
    hn.x = sigf(go.x) * tanh_f(cn.x);
    hn.y = sigf(go.y) * tanh_f(cn.y);
    hn.z = sigf(go.z) * tanh_f(cn.z);
    hn.w = sigf(go.w) * tanh_f(cn.w);
    if (sel == 0) c00 = cn; else if (sel == 1) c01 = cn;
    else if (sel == 2) c10 = cn; else c11 = cn;
    *reinterpret_cast<float4*>(&s.zbuf[bat][r][64 + base]) = hn;
  }
  __syncwarp();
}

__global__ void __launch_bounds__(NT, 1)
stgnn_kernel(const float* __restrict__ x, const float* __restrict__ adj,
             const float* __restrict__ Wenc_g, const float* __restrict__ benc_g,
             const float* __restrict__ Wg1_g, const float* __restrict__ bg1_g,
             const float* __restrict__ Wg2_g, const float* __restrict__ bg2_g,
             const float* __restrict__ Wih_g, const float* __restrict__ Whh_g,
             const float* __restrict__ bih_g, const float* __restrict__ bhh_g,
             const float* __restrict__ Wd1_g, const float* __restrict__ bd1_g,
             const float* __restrict__ Wd2_g, const float* __restrict__ bd2_g,
             float* __restrict__ out, int B) {
  extern __shared__ __align__(16) unsigned char smem_raw[];
  Smem& s = *reinterpret_cast<Smem*>(smem_raw);
  const int tid = threadIdx.x;
  const int b0 = 2 * blockIdx.x;
  const int b1 = min(b0 + 1, B - 1);   // clamp for odd B (duplicate work)
  const int r = tid >> 3;
  const int j = tid & 7;
  const int w = tid >> 5;
  const int lane = tid & 31;
  const int kc = lane >> 3;
  const int cg = lane & 7;
  const int colbase = 32 * w + 4 * cg;

  // ---- one-time per-CTA setup ----
  for (int i = tid; i < INF * 64; i += NT) (&s.Wenc[0][0])[i] = Wenc_g[i];
  for (int i = tid; i < 64 * 64; i += NT) (&s.Wg1[0][0])[i] = Wg1_g[i];
  for (int i = tid; i < 64 * 64; i += NT) (&s.Wg2[0][0])[i] = Wg2_g[i];
  for (int i = tid; i < 64 * 32; i += NT) (&s.Wd1[0][0])[i] = Wd1_g[i];
  if (tid < 192) s.Wd2[tid / 6][tid % 6] = Wd2_g[tid];
  if (tid < 64) {
    s.benc[tid] = benc_g[tid];
    s.bg1[tid] = bg1_g[tid];
    s.bg2[tid] = bg2_g[tid];
  }
  if (tid < 32) s.bd1[tid] = bd1_g[tid];
  if (tid < 6) s.bd2[tid] = bd2_g[tid];
  if (tid < 32) {
    float sum = 0.f;
    for (int jj = 0; jj < 32; jj++)
      sum += (jj == tid) ? 1.f : adj[tid * 32 + jj];
    s.dvec[tid] = rsqrtf(fmaxf(sum, 1.f));
  }
  for (int i = tid; i < 2 * 32 * LDZ; i += NT) (&s.zbuf[0][0][0])[i] = 0.f;
  __syncthreads();
  for (int i = tid; i < 32 * 32; i += NT) {
    int ii = i >> 5, jj = i & 31;
    float a = (ii == jj) ? 1.f : adj[i];
    s.Ahat[ii][jj] = s.dvec[ii] * a * s.dvec[jj];
  }

  // LSTM weights: 4 cols x 32-k quarter (rotation baked in), shared by both
  // batches. Full k-vector for col c: k<64 -> W_ih[c][k], else W_hh[c][k-64].
  p2 wk[4][16];
  float4 bb4;
  int zoff[8];
#pragma unroll
  for (int i = 0; i < 8; i++) {
    int lc = (i + 2 * kc) & 7;
    zoff[i] = kc * 32 + lc * 4;
  }
  {
    const float* base =
        (kc < 2) ? (Wih_g + (size_t)kc * 32) : (Whh_g + (size_t)(kc - 2) * 32);
    float bbv[4];
#pragma unroll
    for (int cc = 0; cc < 4; cc++) {
      int c = colbase + cc;
      bbv[cc] = bih_g[c] + bhh_g[c];
      const float* src = base + (size_t)c * 64;
#pragma unroll
      for (int i = 0; i < 8; i++) {
        int lc = (i + 2 * kc) & 7;
        wk[cc][2 * i]     = pack2(src[lc * 4],     src[lc * 4 + 1]);
        wk[cc][2 * i + 1] = pack2(src[lc * 4 + 2], src[lc * 4 + 3]);
      }
    }
    bb4 = make_float4(bbv[0], bbv[1], bbv[2], bbv[3]);
  }
  float4 c00 = make_float4(0.f, 0.f, 0.f, 0.f), c01 = c00;
  float4 c10 = c00, c11 = c00;
  __syncthreads();

  // ---- encoder: 48 steps ----
  for (int t = 0; t < TT; t++) {
    const float* xt0 = x + ((size_t)b0 * TT + t) * (NNODE * INF);
    const float* xt1 = x + ((size_t)b1 * TT + t) * (NNODE * INF);
    s.xbuf[0][r][j] = xt0[r * INF + j];
    s.xbuf[1][r][j] = xt1[r * INF + j];
    if (j < 3) {
      s.xbuf[0][r][j + 8] = xt0[r * INF + j + 8];
      s.xbuf[1][r][j + 8] = xt1[r * INF + j + 8];
    }
    __syncwarp();
    step2(s, wk, bb4, zoff, c00, c01, c10, c11, tid, colbase, lane);
  }

  // ---- decoder: 48 steps ----
  for (int f = 0; f < FUT; f++) {
    step2(s, wk, bb4, zoff, c00, c01, c10, c11, tid, colbase, lane);
    // h1 = relu(hx @ W_d1 + b_d1), hx row-local in zbuf[bat][r][64..128)
    rowmm2x2<64, 32, true, true, false>(&s.zbuf[0][r][64], &s.zbuf[1][r][64],
                                        &s.Wd1[0][0], s.bd1,
                                        &s.h1[0][r][0], &s.h1[1][r][0], j);
    __syncthreads();
    // res = h1 @ W_d2 + b_d2 ; pred += res ; emit (both batches)
    if (tid < 192) {
      int rr = tid / 6, d = tid - rr * 6;
      float acc0 = s.bd2[d], acc1 = s.bd2[d];
#pragma unroll
      for (int k = 0; k < 32; k++) {
        float wv = s.Wd2[k][d];
        acc0 += s.h1[0][rr][k] * wv;
        acc1 += s.h1[1][rr][k] * wv;
      }
      float p0 = s.xbuf[0][rr][d] + acc0;
      float p1 = s.xbuf[1][rr][d] + acc1;
      s.xbuf[0][rr][d] = p0;
      s.xbuf[1][rr][d] = p1;
      out[(((size_t)b0 * FUT + f) * NNODE + rr) * 6 + d] = p0;
      out[(((size_t)b1 * FUT + f) * NNODE + rr) * 6 + d] = p1;
    }
    __syncthreads();
  }
}

extern "C" void kernel_launch(void* const* d_in, const int* in_sizes, int n_in,
                              void* d_out, int out_size) {
  const float* x    = (const float*)d_in[0];
  const float* adj  = (const float*)d_in[1];
  const float* Wenc = (const float*)d_in[2];
  const float* benc = (const float*)d_in[3];
  const float* Wg1  = (const float*)d_in[4];
  const float* bg1  = (const float*)d_in[5];
  const float* Wg2  = (const float*)d_in[6];
  const float* bg2  = (const float*)d_in[7];
  const float* Wih  = (const float*)d_in[8];
  const float* Whh  = (const float*)d_in[9];
  const float* bih  = (const float*)d_in[10];
  const float* bhh  = (const float*)d_in[11];
  const float* Wd1  = (const float*)d_in[12];
  const float* bd1  = (const float*)d_in[13];
  const float* Wd2  = (const float*)d_in[14];
  const float* bd2  = (const float*)d_in[15];
  float* out = (float*)d_out;

  int B = in_sizes[0] / (TT * NNODE * INF);
  int nblk = (B + 1) / 2;

  cudaFuncSetAttribute(stgnn_kernel,
                       cudaFuncAttributeMaxDynamicSharedMemorySize,
                       (int)sizeof(Smem));
  stgnn_kernel<<<nblk, NT, sizeof(Smem)>>>(x, adj, Wenc, benc, Wg1, bg1, Wg2,
                                           bg2, Wih, Whh, bih, bhh, Wd1, bd1,
                                           Wd2, bd2, out, B);
}